// round 5
// baseline (speedup 1.0000x reference)
#include <cuda_runtime.h>
#include <cuda_bf16.h>
#include <cstdint>
#include <math.h>

#define SEQ 4096
#define H 2048
#define IN_DIM 2048
#define G3 6144

// ---------------- scratch ---------------------------------------------------
__device__ float g_igates[(size_t)SEQ * G3];   // ~100.7 MB
__device__ unsigned int g_bar;

__global__ void init_bar_kernel() { g_bar = 0u; }

// ---------------- Kernel 1: igates = xs @ Wi^T + bi (round-2 proven) -------
#define GBM 128
#define GBN 128
#define GBK 16

__global__ __launch_bounds__(256) void igates_gemm(
    const float* __restrict__ A,
    const float* __restrict__ B,
    const float* __restrict__ bias)
{
    __shared__ float As[GBK][GBM + 1];
    __shared__ float Bs[GBK][GBN + 1];

    const int bm = blockIdx.y * GBM;
    const int bn = blockIdx.x * GBN;
    const int tid = threadIdx.x;
    const int tx = tid & 15;
    const int ty = tid >> 4;
    const int lr = tid >> 2;
    const int lc = tid & 3;

    float acc[8][8];
    #pragma unroll
    for (int i = 0; i < 8; i++)
        #pragma unroll
        for (int j = 0; j < 8; j++) acc[i][j] = 0.f;

    for (int k0 = 0; k0 < IN_DIM; k0 += GBK) {
        #pragma unroll
        for (int s = 0; s < 2; s++) {
            const int row = lr + 64 * s;
            float4 va = *(const float4*)(A + (size_t)(bm + row) * IN_DIM + k0 + 4 * lc);
            As[4*lc+0][row] = va.x; As[4*lc+1][row] = va.y;
            As[4*lc+2][row] = va.z; As[4*lc+3][row] = va.w;
            float4 vb = *(const float4*)(B + (size_t)(bn + row) * IN_DIM + k0 + 4 * lc);
            Bs[4*lc+0][row] = vb.x; Bs[4*lc+1][row] = vb.y;
            Bs[4*lc+2][row] = vb.z; Bs[4*lc+3][row] = vb.w;
        }
        __syncthreads();

        #pragma unroll
        for (int k = 0; k < GBK; k++) {
            float a[8], b[8];
            #pragma unroll
            for (int i = 0; i < 8; i++) a[i] = As[k][ty * 8 + i];
            #pragma unroll
            for (int j = 0; j < 8; j++) b[j] = Bs[k][tx * 8 + j];
            #pragma unroll
            for (int i = 0; i < 8; i++)
                #pragma unroll
                for (int j = 0; j < 8; j++) acc[i][j] += a[i] * b[j];
        }
        __syncthreads();
    }

    #pragma unroll
    for (int i = 0; i < 8; i++) {
        const int row = bm + ty * 8 + i;
        const int col = bn + tx * 8;
        float4 o0, o1;
        o0.x = acc[i][0] + bias[col + 0];
        o0.y = acc[i][1] + bias[col + 1];
        o0.z = acc[i][2] + bias[col + 2];
        o0.w = acc[i][3] + bias[col + 3];
        o1.x = acc[i][4] + bias[col + 4];
        o1.y = acc[i][5] + bias[col + 5];
        o1.z = acc[i][6] + bias[col + 6];
        o1.w = acc[i][7] + bias[col + 7];
        float* cp = g_igates + (size_t)row * G3 + col;
        *(float4*)(cp + 0) = o0;
        *(float4*)(cp + 4) = o1;
    }
}

// ---------------- Kernel 2: persistent GRU recurrence ----------------------
// 128 CTAs (1/SM). Each owns 16 hidden indices => 48 Wh rows cached in SMEM
// as packed bf16 (192 KB). h_{t-1} held in REGISTERS (64 floats/lane);
// bf16 expanded with shift/mask on the ALU pipe; fp32 fmaf accumulate.
#define NCTA 128
#define PER 16
#define NROWS 48
#define RTH 256

__device__ __forceinline__ float bf_lo(unsigned w) {
    return __uint_as_float(w << 16);
}
__device__ __forceinline__ float bf_hi(unsigned w) {
    return __uint_as_float(w & 0xFFFF0000u);
}

__global__ __launch_bounds__(RTH, 1) void gru_recur(
    const float* __restrict__ init_state,
    const float* __restrict__ Wh,
    const float* __restrict__ bn,
    float* __restrict__ out)
{
    extern __shared__ float smem[];
    unsigned* wc = (unsigned*)smem;                       // NROWS * H/2 words
    float* red   = (float*)(wc + (size_t)NROWS * (H/2));  // NROWS floats

    const int tid  = threadIdx.x;
    const int lane = tid & 31;
    const int wid  = tid >> 5;
    const int base = blockIdx.x * PER;
    const int r0   = wid * 6;            // this warp's 6 rows

    // prologue: convert+cache 48 Wh rows as packed bf16 (lo=elem 2v, hi=2v+1)
    for (int r = 0; r < NROWS; r++) {
        const int gate = r / PER, i = r % PER;
        const float2* src = (const float2*)(Wh + (size_t)(gate * H + base + i) * H);
        unsigned* dst = wc + (size_t)r * (H / 2);
        for (int v = tid; v < H / 2; v += RTH) {
            float2 w = src[v];
            __nv_bfloat162 b2 = __floats2bfloat162_rn(w.x, w.y);
            dst[v] = *(unsigned*)&b2;
        }
    }
    __syncthreads();   // REQUIRED: order prologue wc writes vs t=0 reads
                       // (missing in rounds 3/4 -> race -> NaN)

    float bnv = 0.f, lastv = 0.f;
    if (tid < PER) bnv = bn[base + tid];

    for (int t = 0; t < SEQ; t++) {
        const float* hprev = (t == 0) ? init_state : (out + (size_t)(t - 1) * H);

        // early reads: igates (DRAM) + own h_{t-1}; consumed in the epilogue
        float gr = 0.f, gz = 0.f, gn = 0.f, hmine = 0.f;
        if (tid < PER) {
            const float* ig = g_igates + (size_t)t * G3;
            gr = ig[base + tid];
            gz = ig[H + base + tid];
            gn = ig[2 * H + base + tid];
            hmine = __ldcg(hprev + base + tid);
        }

        // ---- load full h_{t-1} into registers (64 floats/lane) ----
        float hreg[64];
        const float4* h4 = (const float4*)hprev;
        #pragma unroll
        for (int j = 0; j < 8; j++) {
            float4 a = __ldcg(h4 + ((j * 32 + lane) * 2 + 0));
            float4 b = __ldcg(h4 + ((j * 32 + lane) * 2 + 1));
            hreg[j * 8 + 0] = a.x; hreg[j * 8 + 1] = a.y;
            hreg[j * 8 + 2] = a.z; hreg[j * 8 + 3] = a.w;
            hreg[j * 8 + 4] = b.x; hreg[j * 8 + 5] = b.y;
            hreg[j * 8 + 6] = b.z; hreg[j * 8 + 7] = b.w;
        }

        // ---- 6 dot products per warp (weights from SMEM, h from regs) ----
        #pragma unroll
        for (int r = 0; r < 6; r++) {
            const uint4* wp = (const uint4*)(wc + (size_t)(r0 + r) * (H / 2));
            float s0 = 0.f, s1 = 0.f, s2 = 0.f, s3 = 0.f;
            float s4 = 0.f, s5 = 0.f, s6 = 0.f, s7 = 0.f;
            #pragma unroll
            for (int j = 0; j < 8; j++) {
                uint4 w4 = wp[j * 32 + lane];       // 8 bf16 = h elems [8j..8j+7]
                s0 = fmaf(bf_lo(w4.x), hreg[j * 8 + 0], s0);
                s1 = fmaf(bf_hi(w4.x), hreg[j * 8 + 1], s1);
                s2 = fmaf(bf_lo(w4.y), hreg[j * 8 + 2], s2);
                s3 = fmaf(bf_hi(w4.y), hreg[j * 8 + 3], s3);
                s4 = fmaf(bf_lo(w4.z), hreg[j * 8 + 4], s4);
                s5 = fmaf(bf_hi(w4.z), hreg[j * 8 + 5], s5);
                s6 = fmaf(bf_lo(w4.w), hreg[j * 8 + 6], s6);
                s7 = fmaf(bf_hi(w4.w), hreg[j * 8 + 7], s7);
            }
            float s = ((s0 + s1) + (s2 + s3)) + ((s4 + s5) + (s6 + s7));
            #pragma unroll
            for (int o = 16; o; o >>= 1) s += __shfl_xor_sync(0xffffffffu, s, o);
            if (lane == 0) red[r0 + r] = s;
        }
        __syncthreads();

        // ---- gate math + write h_t ----
        if (tid < PER) {
            const float hr = red[tid], hz = red[PER + tid], hn = red[2 * PER + tid];
            const float reset  = 1.f / (1.f + expf(-(gr + hr)));
            const float update = 1.f / (1.f + expf(-(gz + hz)));
            const float nv = tanhf(gn + reset * (hn + bnv));
            const float hnext = (1.f - update) * nv + update * hmine;
            __stcg(out + (size_t)t * H + base + tid, hnext);
            lastv = hnext;
        }
        __threadfence();
        __syncthreads();

        // ---- grid barrier ----
        if (tid == 0) {
            atomicAdd(&g_bar, 1u);
            const unsigned target = (unsigned)(t + 1) * NCTA;
            while (*((volatile unsigned int*)&g_bar) < target) { }
            __threadfence();
        }
        __syncthreads();
    }

    if (tid < PER) out[(size_t)SEQ * H + base + tid] = lastv;
}

// ---------------- launch -----------------------------------------------------
extern "C" void kernel_launch(void* const* d_in, const int* in_sizes, int n_in,
                              void* d_out, int out_size)
{
    const float* xs         = (const float*)d_in[0];
    const float* init_state = (const float*)d_in[1];
    const float* Wi         = (const float*)d_in[2];
    const float* Wh         = (const float*)d_in[3];
    const float* bi         = (const float*)d_in[4];
    const float* bn         = (const float*)d_in[5];
    float* out = (float*)d_out;

    init_bar_kernel<<<1, 1>>>();

    dim3 ggrid(G3 / GBN, SEQ / GBM);
    igates_gemm<<<ggrid, 256>>>(xs, Wi, bi);

    const size_t smem = (size_t)NROWS * (H / 2) * sizeof(unsigned)
                      + NROWS * sizeof(float);            // ~192.2 KB
    cudaFuncSetAttribute(gru_recur, cudaFuncAttributeMaxDynamicSharedMemorySize,
                         (int)smem);
    gru_recur<<<NCTA, RTH, smem>>>(init_state, Wh, bn, out);
}